// round 8
// baseline (speedup 1.0000x reference)
#include <cuda_runtime.h>
#include <cuda_bf16.h>

// DistortionLoss (eff_distloss) — two-kernel + PDL overlap.
//
// R7 -> R8: ncu showed dl_finalize_kernel costs 6.5us, nearly all launch
// latency (grid=1, 0.1% of every resource). Main kernel is already at
// ~7.0 TB/s (streaming ceiling). Fix: launch finalize with PROGRAMMATIC
// DEPENDENT LAUNCH so its launch/ramp overlaps the primary's tail; finalize
// calls cudaGridDependencySynchronize() before reading the partials.
// Everything else identical to R7 (unconditional per-block partial stores,
// no init kernel, pair-unrolled 6x LDG.128 main loop, 4096x256 grid).

#define LOSS_WEIGHT 0.01f
#define N_SAMPLES 128
#define GRID_MAX 4096
#define BLOCK_THREADS 256

__device__ double g_partials[GRID_MAX];

__device__ __forceinline__ float row_contrib(
    const float4 wv, const float4 mv, const float4 sv, const int lane)
{
    // uni term partial: sum s*w^2 over this lane's 4 elements
    float uni = sv.x * wv.x * wv.x;
    uni = fmaf(sv.y * wv.y, wv.y, uni);
    uni = fmaf(sv.z * wv.z, wv.z, uni);
    uni = fmaf(sv.w * wv.w, wv.w, uni);

    // wm = w * m
    const float wm0 = wv.x * mv.x;
    const float wm1 = wv.y * mv.y;
    const float wm2 = wv.z * mv.z;
    const float wm3 = wv.w * mv.w;

    // local exclusive prefixes within the 4-element chunk
    const float eW1 = wv.x;
    const float eW2 = eW1 + wv.y;
    const float eW3 = eW2 + wv.z;
    const float tW  = eW3 + wv.w;     // lane total of w

    const float eM1 = wm0;
    const float eM2 = eM1 + wm1;
    const float eM3 = eM2 + wm2;
    const float tM  = eM3 + wm3;      // lane total of wm

    // warp inclusive scan of lane totals (w and wm together; independent
    // chains pipeline their SHFL latencies)
    float iW = tW, iM = tM;
    #pragma unroll
    for (int off = 1; off < 32; off <<= 1) {
        const float aW = __shfl_up_sync(0xffffffffu, iW, off);
        const float aM = __shfl_up_sync(0xffffffffu, iM, off);
        if (lane >= off) { iW += aW; iM += aM; }
    }
    const float EW = iW - tW;   // exclusive warp prefix of w
    const float EM = iM - tM;   // exclusive warp prefix of wm

    // bi term: sum_k wm_k * exW_k - w_k * exWM_k  (exclusive prefixes)
    float bi;
    bi  = wm0 * EW          - wv.x * EM;
    bi += wm1 * (EW + eW1)  - wv.y * (EM + eM1);
    bi += wm2 * (EW + eW2)  - wv.z * (EM + eM2);
    bi += wm3 * (EW + eW3)  - wv.w * (EM + eM3);

    return (1.0f / 3.0f) * uni + 2.0f * bi;
}

__global__ __launch_bounds__(BLOCK_THREADS) void dl_main_kernel(
    const float* __restrict__ w,
    const float* __restrict__ m,
    const float* __restrict__ s,
    int B)
{
    const int lane   = threadIdx.x & 31;
    const int warpIn = threadIdx.x >> 5;
    const int gwarp  = (blockIdx.x * BLOCK_THREADS + threadIdx.x) >> 5;
    const int nwarps = (gridDim.x * BLOCK_THREADS) >> 5;

    float acc = 0.0f;

    // Row-pair loop: warp handles rows (2g, 2g+1), stride 2*nwarps.
    int row = 2 * gwarp;
    for (; row + 1 < B; row += 2 * nwarps) {
        const size_t b0 = (size_t)row * N_SAMPLES;
        const size_t b1 = b0 + N_SAMPLES;
        // 6 independent 16B loads issued before any compute
        const float4 wv0 = reinterpret_cast<const float4*>(w + b0)[lane];
        const float4 wv1 = reinterpret_cast<const float4*>(w + b1)[lane];
        const float4 mv0 = reinterpret_cast<const float4*>(m + b0)[lane];
        const float4 mv1 = reinterpret_cast<const float4*>(m + b1)[lane];
        const float4 sv0 = reinterpret_cast<const float4*>(s + b0)[lane];
        const float4 sv1 = reinterpret_cast<const float4*>(s + b1)[lane];

        acc += row_contrib(wv0, mv0, sv0, lane);
        acc += row_contrib(wv1, mv1, sv1, lane);
    }
    if (row < B) {  // odd-B tail
        const size_t b0 = (size_t)row * N_SAMPLES;
        const float4 wv0 = reinterpret_cast<const float4*>(w + b0)[lane];
        const float4 mv0 = reinterpret_cast<const float4*>(m + b0)[lane];
        const float4 sv0 = reinterpret_cast<const float4*>(s + b0)[lane];
        acc += row_contrib(wv0, mv0, sv0, lane);
    }

    // warp reduce
    #pragma unroll
    for (int off = 16; off > 0; off >>= 1)
        acc += __shfl_down_sync(0xffffffffu, acc, off);

    __shared__ float warp_sums[BLOCK_THREADS / 32];
    if (lane == 0) warp_sums[warpIn] = acc;
    __syncthreads();

    if (threadIdx.x == 0) {
        float blockAcc = 0.0f;
        #pragma unroll
        for (int i = 0; i < BLOCK_THREADS / 32; i++) blockAcc += warp_sums[i];
        // Unconditional store: every launch writes every slot -> no init pass.
        g_partials[blockIdx.x] = (double)blockAcc;
    }
}

__global__ __launch_bounds__(BLOCK_THREADS) void dl_finalize_kernel(
    float* __restrict__ out, int nPartials, float scale)
{
    // PDL: we may be running before the primary kernel finished. Block until
    // the primary grid's memory operations are visible, then reduce.
    cudaGridDependencySynchronize();

    const int lane   = threadIdx.x & 31;
    const int warpIn = threadIdx.x >> 5;

    double t = 0.0;
    for (int i = threadIdx.x; i < nPartials; i += BLOCK_THREADS)
        t += g_partials[i];

    #pragma unroll
    for (int off = 16; off > 0; off >>= 1)
        t += __shfl_down_sync(0xffffffffu, t, off);

    __shared__ double dsums[BLOCK_THREADS / 32];
    if (lane == 0) dsums[warpIn] = t;
    __syncthreads();

    if (threadIdx.x == 0) {
        double total = 0.0;
        #pragma unroll
        for (int i = 0; i < BLOCK_THREADS / 32; i++) total += dsums[i];
        out[0] = (float)(total * (double)scale);
    }
}

extern "C" void kernel_launch(void* const* d_in, const int* in_sizes, int n_in,
                              void* d_out, int out_size) {
    const float* w = (const float*)d_in[0];
    const float* m = (const float*)d_in[1];
    const float* s = (const float*)d_in[2];
    float* out = (float*)d_out;

    const int B = in_sizes[0] / N_SAMPLES;

    const int warpsPerBlock = BLOCK_THREADS / 32;
    const int maxUseful = (B + 1) / 2;              // row pairs
    int blocks = GRID_MAX;
    if (blocks * warpsPerBlock > maxUseful) {
        blocks = (maxUseful + warpsPerBlock - 1) / warpsPerBlock;
        if (blocks < 1) blocks = 1;
    }

    dl_main_kernel<<<blocks, BLOCK_THREADS>>>(w, m, s, B);

    // Launch finalize with Programmatic Dependent Launch so its launch
    // latency overlaps the primary's tail. Captured as a programmatic edge
    // in the CUDA graph.
    cudaLaunchConfig_t cfg = {};
    cfg.gridDim  = dim3(1, 1, 1);
    cfg.blockDim = dim3(BLOCK_THREADS, 1, 1);
    cfg.dynamicSmemBytes = 0;
    cfg.stream = 0;
    cudaLaunchAttribute attrs[1];
    attrs[0].id = cudaLaunchAttributeProgrammaticStreamSerialization;
    attrs[0].val.programmaticStreamSerializationAllowed = 1;
    cfg.attrs = attrs;
    cfg.numAttrs = 1;

    const float scale = LOSS_WEIGHT / (float)B;
    cudaError_t err = cudaLaunchKernelEx(&cfg, dl_finalize_kernel,
                                         out, blocks, scale);
    if (err != cudaSuccess) {
        // Fallback: plain serialized launch (still correct).
        dl_finalize_kernel<<<1, BLOCK_THREADS>>>(out, blocks, scale);
    }
}

// round 9
// speedup vs baseline: 1.0329x; 1.0329x over previous
#include <cuda_runtime.h>
#include <cuda_bf16.h>

// DistortionLoss (eff_distloss) — atomic-accumulate + O(1) finalize.
//
// R8 -> R9: PDL gained nothing; the 6.5-7.4us finalize cost is mostly its own
// execution (one block pulling 4096 doubles at memory latency). Replace the
// partials array with a single device-wide fp64 red-add accumulator:
//  - main kernel: each block does ONE atomicAdd(&g_accum, partial) -> REDG,
//    ~0.854cyc/op single-address, fully hidden under the streaming tail.
//  - finalize: 1 thread reads g_accum, writes out scaled, then RESETS
//    g_accum=0 so the next graph replay starts clean (deterministic:
//    every launch begins at 0 and ends at 0; no zero kernel needed).
// Main loop unchanged (pair-unrolled, 6 independent LDG.128/iter, 4096x256).

#define LOSS_WEIGHT 0.01f
#define N_SAMPLES 128
#define GRID_MAX 4096
#define BLOCK_THREADS 256

__device__ double g_accum = 0.0;   // always 0 between launches

__device__ __forceinline__ float row_contrib(
    const float4 wv, const float4 mv, const float4 sv, const int lane)
{
    // uni term partial: sum s*w^2 over this lane's 4 elements
    float uni = sv.x * wv.x * wv.x;
    uni = fmaf(sv.y * wv.y, wv.y, uni);
    uni = fmaf(sv.z * wv.z, wv.z, uni);
    uni = fmaf(sv.w * wv.w, wv.w, uni);

    // wm = w * m
    const float wm0 = wv.x * mv.x;
    const float wm1 = wv.y * mv.y;
    const float wm2 = wv.z * mv.z;
    const float wm3 = wv.w * mv.w;

    // local exclusive prefixes within the 4-element chunk
    const float eW1 = wv.x;
    const float eW2 = eW1 + wv.y;
    const float eW3 = eW2 + wv.z;
    const float tW  = eW3 + wv.w;     // lane total of w

    const float eM1 = wm0;
    const float eM2 = eM1 + wm1;
    const float eM3 = eM2 + wm2;
    const float tM  = eM3 + wm3;      // lane total of wm

    // warp inclusive scan of lane totals (w and wm together; independent
    // chains pipeline their SHFL latencies)
    float iW = tW, iM = tM;
    #pragma unroll
    for (int off = 1; off < 32; off <<= 1) {
        const float aW = __shfl_up_sync(0xffffffffu, iW, off);
        const float aM = __shfl_up_sync(0xffffffffu, iM, off);
        if (lane >= off) { iW += aW; iM += aM; }
    }
    const float EW = iW - tW;   // exclusive warp prefix of w
    const float EM = iM - tM;   // exclusive warp prefix of wm

    // bi term: sum_k wm_k * exW_k - w_k * exWM_k  (exclusive prefixes)
    float bi;
    bi  = wm0 * EW          - wv.x * EM;
    bi += wm1 * (EW + eW1)  - wv.y * (EM + eM1);
    bi += wm2 * (EW + eW2)  - wv.z * (EM + eM2);
    bi += wm3 * (EW + eW3)  - wv.w * (EM + eM3);

    return (1.0f / 3.0f) * uni + 2.0f * bi;
}

__global__ __launch_bounds__(BLOCK_THREADS) void dl_main_kernel(
    const float* __restrict__ w,
    const float* __restrict__ m,
    const float* __restrict__ s,
    int B)
{
    const int lane   = threadIdx.x & 31;
    const int warpIn = threadIdx.x >> 5;
    const int gwarp  = (blockIdx.x * BLOCK_THREADS + threadIdx.x) >> 5;
    const int nwarps = (gridDim.x * BLOCK_THREADS) >> 5;

    float acc = 0.0f;

    // Row-pair loop: warp handles rows (2g, 2g+1), stride 2*nwarps.
    int row = 2 * gwarp;
    for (; row + 1 < B; row += 2 * nwarps) {
        const size_t b0 = (size_t)row * N_SAMPLES;
        const size_t b1 = b0 + N_SAMPLES;
        // 6 independent 16B loads issued before any compute
        const float4 wv0 = reinterpret_cast<const float4*>(w + b0)[lane];
        const float4 wv1 = reinterpret_cast<const float4*>(w + b1)[lane];
        const float4 mv0 = reinterpret_cast<const float4*>(m + b0)[lane];
        const float4 mv1 = reinterpret_cast<const float4*>(m + b1)[lane];
        const float4 sv0 = reinterpret_cast<const float4*>(s + b0)[lane];
        const float4 sv1 = reinterpret_cast<const float4*>(s + b1)[lane];

        acc += row_contrib(wv0, mv0, sv0, lane);
        acc += row_contrib(wv1, mv1, sv1, lane);
    }
    if (row < B) {  // odd-B tail
        const size_t b0 = (size_t)row * N_SAMPLES;
        const float4 wv0 = reinterpret_cast<const float4*>(w + b0)[lane];
        const float4 mv0 = reinterpret_cast<const float4*>(m + b0)[lane];
        const float4 sv0 = reinterpret_cast<const float4*>(s + b0)[lane];
        acc += row_contrib(wv0, mv0, sv0, lane);
    }

    // warp reduce
    #pragma unroll
    for (int off = 16; off > 0; off >>= 1)
        acc += __shfl_down_sync(0xffffffffu, acc, off);

    __shared__ float warp_sums[BLOCK_THREADS / 32];
    if (lane == 0) warp_sums[warpIn] = acc;
    __syncthreads();

    if (threadIdx.x == 0) {
        float blockAcc = 0.0f;
        #pragma unroll
        for (int i = 0; i < BLOCK_THREADS / 32; i++) blockAcc += warp_sums[i];
        atomicAdd(&g_accum, (double)blockAcc);   // REDG, single address
    }
}

__global__ void dl_finalize_kernel(float* __restrict__ out, float scale) {
    out[0] = (float)(g_accum * (double)scale);
    g_accum = 0.0;   // leave accumulator clean for the next replay
}

extern "C" void kernel_launch(void* const* d_in, const int* in_sizes, int n_in,
                              void* d_out, int out_size) {
    const float* w = (const float*)d_in[0];
    const float* m = (const float*)d_in[1];
    const float* s = (const float*)d_in[2];
    float* out = (float*)d_out;

    const int B = in_sizes[0] / N_SAMPLES;

    const int warpsPerBlock = BLOCK_THREADS / 32;
    const int maxUseful = (B + 1) / 2;              // row pairs
    int blocks = GRID_MAX;
    if (blocks * warpsPerBlock > maxUseful) {
        blocks = (maxUseful + warpsPerBlock - 1) / warpsPerBlock;
        if (blocks < 1) blocks = 1;
    }

    dl_main_kernel<<<blocks, BLOCK_THREADS>>>(w, m, s, B);
    dl_finalize_kernel<<<1, 1>>>(out, LOSS_WEIGHT / (float)B);
}